// round 17
// baseline (speedup 1.0000x reference)
#include <cuda_runtime.h>
#include <cuda_bf16.h>
#include <cstdint>

// Problem constants
#define B_  64
#define S_  2048
#define E_  256
#define H_  256
#define M_TOT (B_ * S_)        // 131072 rows

typedef unsigned long long u64t;

// Scratch (device-global: runtime allocation is forbidden)
__device__ float         g_xw [(size_t)M_TOT * H_];   // 128 MB
__device__ __nv_bfloat16 g_Whi[H_ * E_];
__device__ __nv_bfloat16 g_Wlo[H_ * E_];
__device__ float2        g_Uw2[(H_ / 2) * H_];        // [pair p][h] = (Uw[h][2p], Uw[h][2p+1])

// Fast tanh: 1 - 2/(e^{2x}+1). |err| ~1e-6; exact saturation at +/-inf.
__device__ __forceinline__ float fast_tanh(float x) {
    float e = __expf(2.0f * x);
    float r;
    asm("rcp.approx.f32 %0, %1;" : "=f"(r) : "f"(e + 1.0f));
    return fmaf(-2.0f, r, 1.0f);
}

// Packed fp32 helpers
__device__ __forceinline__ u64t ffma2(u64t a, u64t b, u64t c) {
    u64t d;
    asm("fma.rn.f32x2 %0, %1, %2, %3;" : "=l"(d) : "l"(a), "l"(b), "l"(c));
    return d;
}
__device__ __forceinline__ u64t pack2(float lo, float hi) {
    u64t d;
    asm("mov.b64 %0, {%1, %2};" : "=l"(d) : "f"(lo), "f"(hi));
    return d;
}
__device__ __forceinline__ float2 unpack2(u64t p) {
    float2 r;
    asm("mov.b64 {%0, %1}, %2;" : "=f"(r.x), "=f"(r.y) : "l"(p));
    return r;
}

// ---------------------------------------------------------------------------
// prep (merged): Uw pair-pack + Ww hi/lo split
// ---------------------------------------------------------------------------
__global__ void prep(const float* __restrict__ Uw, const float* __restrict__ Ww) {
    int k = blockIdx.x, h = threadIdx.x;
    float u = Uw[h * H_ + k];
    if (k & 1) g_Uw2[(k >> 1) * H_ + h].y = u;
    else       g_Uw2[(k >> 1) * H_ + h].x = u;
    int i = k * H_ + h;                 // covers H*E = 65536
    float v = Ww[i];
    __nv_bfloat16 hb = __float2bfloat16_rn(v);
    g_Whi[i] = hb;
    g_Wlo[i] = __float2bfloat16_rn(v - __bfloat162float(hb));
}

// ---------------------------------------------------------------------------
// Fused split-bf16 tensor-core GEMM — EXACT R15 version (best measured).
//   xw = x_hi*W_hi + x_lo*W_hi + x_hi*W_lo + Wb
//   CTA tile 128x128, 8 warps = 4(M) x 2(N), warp tile 32x64.
// ---------------------------------------------------------------------------
#define ASTR 40
#define CTM 128
#define CTN 128

__device__ __forceinline__ void ldmx4(uint32_t& r0, uint32_t& r1, uint32_t& r2, uint32_t& r3,
                                      uint32_t addr) {
    asm volatile("ldmatrix.sync.aligned.m8n8.x4.shared.b16 {%0,%1,%2,%3}, [%4];"
                 : "=r"(r0), "=r"(r1), "=r"(r2), "=r"(r3) : "r"(addr));
}
__device__ __forceinline__ void mma16816(float* d, const uint32_t* a,
                                         uint32_t b0, uint32_t b1) {
    asm volatile("mma.sync.aligned.m16n8k16.row.col.f32.bf16.bf16.f32 "
                 "{%0,%1,%2,%3}, {%4,%5,%6,%7}, {%8,%9}, {%0,%1,%2,%3};"
                 : "+f"(d[0]), "+f"(d[1]), "+f"(d[2]), "+f"(d[3])
                 : "r"(a[0]), "r"(a[1]), "r"(a[2]), "r"(a[3]), "r"(b0), "r"(b1));
}

__device__ __forceinline__ void split4(float4 v, uint32_t* hi, uint32_t* lo) {
    __nv_bfloat16 h0 = __float2bfloat16_rn(v.x);
    __nv_bfloat16 h1 = __float2bfloat16_rn(v.y);
    __nv_bfloat16 h2 = __float2bfloat16_rn(v.z);
    __nv_bfloat16 h3 = __float2bfloat16_rn(v.w);
    __nv_bfloat162 H0(h0, h1), H1(h2, h3);
    __nv_bfloat162 L0(__float2bfloat16_rn(v.x - __bfloat162float(h0)),
                      __float2bfloat16_rn(v.y - __bfloat162float(h1)));
    __nv_bfloat162 L1(__float2bfloat16_rn(v.z - __bfloat162float(h2)),
                      __float2bfloat16_rn(v.w - __bfloat162float(h3)));
    hi[0] = *(uint32_t*)&H0; hi[1] = *(uint32_t*)&H1;
    lo[0] = *(uint32_t*)&L0; lo[1] = *(uint32_t*)&L1;
}

__global__ __launch_bounds__(256) void gemm_fused(const float* __restrict__ x,
                                                  const float* __restrict__ Wb) {
    __shared__ __nv_bfloat16 Ahi[CTM * ASTR];
    __shared__ __nv_bfloat16 Alo[CTM * ASTR];
    __shared__ __nv_bfloat16 Bhi[CTN * ASTR];
    __shared__ __nv_bfloat16 Blo[CTN * ASTR];

    const int tid   = threadIdx.x;
    const int lane  = tid & 31;
    const int warp  = tid >> 5;
    const int warpM = warp >> 1;
    const int warpN = warp & 1;
    const int grp   = lane >> 2;
    const int qid   = lane & 3;

    const size_t row0 = (size_t)blockIdx.y * CTM;
    const int    n0   = blockIdx.x * CTN;

    const int arow = tid >> 1, ahalf = (tid & 1) * 16;

    float d[2][8][4];
    #pragma unroll
    for (int i = 0; i < 2; i++)
        #pragma unroll
        for (int j = 0; j < 8; j++)
            #pragma unroll
            for (int c = 0; c < 4; c++) d[i][j][c] = 0.0f;

    uint32_t ah_base = (uint32_t)__cvta_generic_to_shared(Ahi);
    uint32_t al_base = (uint32_t)__cvta_generic_to_shared(Alo);
    uint32_t bh_base = (uint32_t)__cvta_generic_to_shared(Bhi);
    uint32_t bl_base = (uint32_t)__cvta_generic_to_shared(Blo);

    const float* xrow = x + (row0 + arow) * E_ + ahalf;
    const __nv_bfloat16* whrow = g_Whi + (size_t)(n0 + arow) * E_ + ahalf;
    const __nv_bfloat16* wlrow = g_Wlo + (size_t)(n0 + arow) * E_ + ahalf;

    float4 fa0 = *(const float4*)&xrow[0];
    float4 fa1 = *(const float4*)&xrow[4];
    float4 fa2 = *(const float4*)&xrow[8];
    float4 fa3 = *(const float4*)&xrow[12];
    uint4 wh0 = *(const uint4*)&whrow[0];
    uint4 wh1 = *(const uint4*)&whrow[8];
    uint4 wl0 = *(const uint4*)&wlrow[0];
    uint4 wl1 = *(const uint4*)&wlrow[8];

    for (int kc = 0; kc < 8; kc++) {
        {
            uint32_t h[8], l[8];
            split4(fa0, h + 0, l + 0);
            split4(fa1, h + 2, l + 2);
            split4(fa2, h + 4, l + 4);
            split4(fa3, h + 6, l + 6);
            *(uint4*)&Ahi[arow * ASTR + ahalf + 0] = make_uint4(h[0], h[1], h[2], h[3]);
            *(uint4*)&Ahi[arow * ASTR + ahalf + 8] = make_uint4(h[4], h[5], h[6], h[7]);
            *(uint4*)&Alo[arow * ASTR + ahalf + 0] = make_uint4(l[0], l[1], l[2], l[3]);
            *(uint4*)&Alo[arow * ASTR + ahalf + 8] = make_uint4(l[4], l[5], l[6], l[7]);
            *(uint4*)&Bhi[arow * ASTR + ahalf + 0] = wh0;
            *(uint4*)&Bhi[arow * ASTR + ahalf + 8] = wh1;
            *(uint4*)&Blo[arow * ASTR + ahalf + 0] = wl0;
            *(uint4*)&Blo[arow * ASTR + ahalf + 8] = wl1;
        }
        __syncthreads();

        if (kc + 1 < 8) {
            const int ko = (kc + 1) * 32;
            fa0 = *(const float4*)&xrow[ko + 0];
            fa1 = *(const float4*)&xrow[ko + 4];
            fa2 = *(const float4*)&xrow[ko + 8];
            fa3 = *(const float4*)&xrow[ko + 12];
            wh0 = *(const uint4*)&whrow[ko + 0];
            wh1 = *(const uint4*)&whrow[ko + 8];
            wl0 = *(const uint4*)&wlrow[ko + 0];
            wl1 = *(const uint4*)&wlrow[ko + 8];
        }

        #pragma unroll
        for (int k16 = 0; k16 < 32; k16 += 16) {
            uint32_t ahi[2][4], alo[2][4];
            #pragma unroll
            for (int i = 0; i < 2; i++) {
                int r = warpM * 32 + i * 16 + (lane & 15);
                int c = k16 + ((lane >> 4) << 3);
                uint32_t off = (uint32_t)(r * ASTR + c) * 2;
                ldmx4(ahi[i][0], ahi[i][1], ahi[i][2], ahi[i][3], ah_base + off);
                ldmx4(alo[i][0], alo[i][1], alo[i][2], alo[i][3], al_base + off);
            }
            #pragma unroll
            for (int j2 = 0; j2 < 4; j2++) {
                int n = warpN * 64 + j2 * 16 + (((lane >> 4) & 1) << 3) + (lane & 7);
                int c = k16 + (((lane >> 3) & 1) << 3);
                uint32_t off = (uint32_t)(n * ASTR + c) * 2;
                uint32_t bh[4], bl[4];
                ldmx4(bh[0], bh[1], bh[2], bh[3], bh_base + off);
                ldmx4(bl[0], bl[1], bl[2], bl[3], bl_base + off);
                #pragma unroll
                for (int i = 0; i < 2; i++)
                    #pragma unroll
                    for (int sel = 0; sel < 2; sel++) {
                        float* dd = d[i][j2 * 2 + sel];
                        mma16816(dd, ahi[i], bh[sel * 2], bh[sel * 2 + 1]);
                        mma16816(dd, alo[i], bh[sel * 2], bh[sel * 2 + 1]);
                        mma16816(dd, ahi[i], bl[sel * 2], bl[sel * 2 + 1]);
                    }
            }
        }
        __syncthreads();
    }

    #pragma unroll
    for (int j = 0; j < 8; j++) {
        int col = n0 + warpN * 64 + j * 8 + qid * 2;
        float2 wb = *(const float2*)&Wb[col];
        #pragma unroll
        for (int i = 0; i < 2; i++) {
            size_t r = row0 + warpM * 32 + i * 16 + grp;
            float2 o0 = make_float2(d[i][j][0] + wb.x, d[i][j][1] + wb.y);
            float2 o1 = make_float2(d[i][j][2] + wb.x, d[i][j][3] + wb.y);
            *(float2*)&g_xw[r * H_ + col]       = o0;
            *(float2*)&g_xw[(r + 8) * H_ + col] = o1;
        }
    }
}

// ---------------------------------------------------------------------------
// Scan: one CTA per batch, 256 threads. R15 structure, inner loop converted
// to packed fma.rn.f32x2: pairs over k (u-pairs x v-pairs), MOV-free
// orientation. 96 register pair-rows + 32 smem pair-rows. FFMA issues/thread
// halve: 256 -> 128.
// ---------------------------------------------------------------------------
#define PREG 96                        // register-resident k-pairs (= 192 rows)
#define PSM  (H_ / 2 - PREG)           // 32 smem k-pairs (= 64 rows)

// smem: [ su: PSM * H_ u64 ][ vsm: 2 * H_ float ]
#define SMEM_BYTES (PSM * H_ * 8 + 2 * H_ * 4)

__global__ __launch_bounds__(256, 1)
void rnn_scan(const float* __restrict__ Ub,
              float* __restrict__ Out,     // [B,S,H]
              float* __restrict__ Tfin) {  // [B,H]
    extern __shared__ float sm[];
    u64t*  su  = (u64t*)sm;                    // PSM pair-rows x H_
    float* vsm = sm + PSM * H_ * 2;            // 2 x H_ double buffer

    const int tid = threadIdx.x;
    const int b   = blockIdx.x;

    // Register pair-cache: uw2[p] = (Uw[tid][2p], Uw[tid][2p+1])
    u64t uw2[PREG];
    const u64t* Uw2u = (const u64t*)g_Uw2;
    #pragma unroll
    for (int p = 0; p < PREG; p++)
        uw2[p] = Uw2u[p * H_ + tid];

    // smem pairs PREG..127
    for (int r = 0; r < PSM; r++)
        su[r * H_ + tid] = Uw2u[(PREG + r) * H_ + tid];
    __syncthreads();

    const float ub = Ub[tid];
    float t = 0.0f;

    const float* xwp = g_xw + (size_t)b * S_ * H_ + tid;
    float*       op  = Out  + (size_t)b * S_ * H_ + tid;

    float xv = __ldcs(xwp);

    for (int s = 0; s < S_; s++) {
        float v = fast_tanh(xv + t);
        float* vb = vsm + (s & 1) * H_;
        vb[tid] = v;
        __syncthreads();

        if (s + 1 < S_) xv = __ldcs(xwp + (size_t)(s + 1) * H_);

        const float4* v4 = (const float4*)vb;
        u64t a0 = 0, a1 = 0, a2 = 0, a3 = 0, a4 = 0, a5 = 0, a6 = 0, a7 = 0;

        float4 vA = v4[0];
        float4 vB = v4[1];

        // Register section: 48 v-quads (192 rows = 96 pairs), 2-deep v pipe.
        // Each 2-quad group: 4 packed FMAs (8 MACs/lane-pairless... 8 rows).
        #pragma unroll
        for (int q = 0; q < 48; q += 2) {
            float4 nA = v4[q + 2];
            float4 nB = v4[q + 3];
            const int p = 2 * q;
            if (q & 2) {
                a4 = ffma2(uw2[p + 0], pack2(vA.x, vA.y), a4);
                a5 = ffma2(uw2[p + 1], pack2(vA.z, vA.w), a5);
                a6 = ffma2(uw2[p + 2], pack2(vB.x, vB.y), a6);
                a7 = ffma2(uw2[p + 3], pack2(vB.z, vB.w), a7);
            } else {
                a0 = ffma2(uw2[p + 0], pack2(vA.x, vA.y), a0);
                a1 = ffma2(uw2[p + 1], pack2(vA.z, vA.w), a1);
                a2 = ffma2(uw2[p + 2], pack2(vB.x, vB.y), a2);
                a3 = ffma2(uw2[p + 3], pack2(vB.z, vB.w), a3);
            }
            vA = nA; vB = nB;
        }

        // Shared-memory section: 16 v-quads (64 rows = 32 pairs)
        const u64t* up = su + tid;
        #pragma unroll
        for (int q = 48; q < 64; q += 2) {
            float4 nA, nB;
            if (q + 2 < 64) { nA = v4[q + 2]; nB = v4[q + 3]; }
            else            { nA = vA;        nB = vB;        }
            const int r = 2 * q - 2 * 48;     // pair-row offset 0..28
            u64t u0 = up[(r + 0) * H_];
            u64t u1 = up[(r + 1) * H_];
            u64t u2 = up[(r + 2) * H_];
            u64t u3 = up[(r + 3) * H_];
            if (q & 2) {
                a4 = ffma2(u0, pack2(vA.x, vA.y), a4);
                a5 = ffma2(u1, pack2(vA.z, vA.w), a5);
                a6 = ffma2(u2, pack2(vB.x, vB.y), a6);
                a7 = ffma2(u3, pack2(vB.z, vB.w), a7);
            } else {
                a0 = ffma2(u0, pack2(vA.x, vA.y), a0);
                a1 = ffma2(u1, pack2(vA.z, vA.w), a1);
                a2 = ffma2(u2, pack2(vB.x, vB.y), a2);
                a3 = ffma2(u3, pack2(vB.z, vB.w), a3);
            }
            vA = nA; vB = nB;
        }

        float2 e0 = unpack2(a0), e1 = unpack2(a1), e2 = unpack2(a2), e3 = unpack2(a3);
        float2 e4 = unpack2(a4), e5 = unpack2(a5), e6 = unpack2(a6), e7 = unpack2(a7);
        t = ub + (((e0.x + e0.y) + (e1.x + e1.y)) + ((e2.x + e2.y) + (e3.x + e3.y)))
               + (((e4.x + e4.y) + (e5.x + e5.y)) + ((e6.x + e6.y) + (e7.x + e7.y)));

        __stcs(&op[(size_t)s * H_], t);
    }

    Tfin[b * H_ + tid] = t;
}

// ---------------------------------------------------------------------------
// Launcher (serial: merged prep -> R15 GEMM -> packed-FMA scan)
// ---------------------------------------------------------------------------
extern "C" void kernel_launch(void* const* d_in, const int* in_sizes, int n_in,
                              void* d_out, int out_size) {
    const float* x  = (const float*)d_in[0];   // [B,S,E]
    const float* Ww = (const float*)d_in[1];   // [H,E]
    const float* Wb = (const float*)d_in[2];   // [H]
    const float* Uw = (const float*)d_in[3];   // [H,H]
    const float* Ub = (const float*)d_in[4];   // [H]

    float* out  = (float*)d_out;
    float* tfin = out;                          // [B,H]
    float* O    = out + (size_t)B_ * H_;        // [B,S,H]

    cudaFuncSetAttribute(rnn_scan, cudaFuncAttributeMaxDynamicSharedMemorySize,
                         SMEM_BYTES);

    prep<<<H_, H_>>>(Uw, Ww);
    gemm_fused<<<dim3(H_ / CTN, M_TOT / CTM), 256>>>(x, Wb);
    rnn_scan<<<B_, 256, SMEM_BYTES>>>(Ub, O, tfin);
}